// round 7
// baseline (speedup 1.0000x reference)
#include <cuda_runtime.h>

// DiscriminatorLoss: out = mean( (s==other_s ? +1 : -1) * x ), N = 33554432.
// HBM/LTS-bound streaming reduction (~402 MB read, measured 6.5 TB/s ~ 94%
// of the LTS path-independent cap).
// Main loop = proven R6 shape: 1024 CTAs x 256 thr, 2-way unroll, __ldcs
// streaming vec4 loads, 31 regs, n4/stride == 32 exactly (zero tail).
// Epilogue: deterministic 64-bit fixed-point atomicAdd (integer addition is
// associative -> bit-identical every replay). Last-ticket block exchanges the
// accumulator back to 0 (self-resetting for graph replay) and writes mean.

#define RBLOCKS 1024
#define RTHREADS 256

__device__ long long    g_accum;    // zero-initialized; reset via atomicExch
__device__ unsigned int g_ticket;   // zero-initialized; wraps back to 0

// 2^32 fixed-point scale for the deterministic integer accumulation.
#define FXSCALE 4294967296.0
#define FXINV   (1.0 / 4294967296.0)

__global__ __launch_bounds__(RTHREADS)
void disc_loss_fused(const int* __restrict__ s,
                     const int* __restrict__ o,
                     const float* __restrict__ x,
                     int n4, float inv_n,
                     float* __restrict__ out)
{
    const int4*   s4 = reinterpret_cast<const int4*>(s);
    const int4*   o4 = reinterpret_cast<const int4*>(o);
    const float4* x4 = reinterpret_cast<const float4*>(x);

    float acc = 0.0f;
    const int stride = gridDim.x * blockDim.x;
    int i = blockIdx.x * blockDim.x + threadIdx.x;

    // 2-way unrolled grid-stride loop: 6 independent 128-bit streaming loads
    // in flight per body. On the bench shape: 16 clean bodies, no tail.
    for (; i + stride < n4; i += 2 * stride) {
        int4   sa = __ldcs(&s4[i]);
        int4   oa = __ldcs(&o4[i]);
        int4   sb = __ldcs(&s4[i + stride]);
        int4   ob = __ldcs(&o4[i + stride]);
        float4 xa = __ldcs(&x4[i]);
        float4 xb = __ldcs(&x4[i + stride]);

        acc += (sa.x == oa.x) ? xa.x : -xa.x;
        acc += (sa.y == oa.y) ? xa.y : -xa.y;
        acc += (sa.z == oa.z) ? xa.z : -xa.z;
        acc += (sa.w == oa.w) ? xa.w : -xa.w;
        acc += (sb.x == ob.x) ? xb.x : -xb.x;
        acc += (sb.y == ob.y) ? xb.y : -xb.y;
        acc += (sb.z == ob.z) ? xb.z : -xb.z;
        acc += (sb.w == ob.w) ? xb.w : -xb.w;
    }
    for (; i < n4; i += stride) {
        int4   sv = __ldcs(&s4[i]);
        int4   ov = __ldcs(&o4[i]);
        float4 xv = __ldcs(&x4[i]);
        acc += (sv.x == ov.x) ? xv.x : -xv.x;
        acc += (sv.y == ov.y) ? xv.y : -xv.y;
        acc += (sv.z == ov.z) ? xv.z : -xv.z;
        acc += (sv.w == ov.w) ? xv.w : -xv.w;
    }

    // Block reduce
    #pragma unroll
    for (int off = 16; off > 0; off >>= 1)
        acc += __shfl_xor_sync(0xffffffffu, acc, off);

    __shared__ float warp_sums[RTHREADS / 32];
    if ((threadIdx.x & 31) == 0)
        warp_sums[threadIdx.x >> 5] = acc;
    __syncthreads();

    if (threadIdx.x == 0) {
        float v = warp_sums[0];
        #pragma unroll
        for (int w = 1; w < RTHREADS / 32; w++)
            v += warp_sums[w];

        // Deterministic fixed-point accumulation: integer adds are
        // associative, so the total is bit-identical on every replay.
        long long q = llrint((double)v * FXSCALE);
        atomicAdd((unsigned long long*)&g_accum, (unsigned long long)q);
        __threadfence();

        // atomicInc wraps: old==RBLOCKS-1 -> 0 (self-resets per replay).
        unsigned int t = atomicInc(&g_ticket, RBLOCKS - 1u);
        if (t == RBLOCKS - 1u) {
            __threadfence();
            // Read total and reset accumulator for the next graph replay.
            long long total =
                (long long)atomicExch((unsigned long long*)&g_accum, 0ull);
            out[0] = (float)((double)total * FXINV * (double)inv_n);
        }
    }
}

extern "C" void kernel_launch(void* const* d_in, const int* in_sizes, int n_in,
                              void* d_out, int out_size)
{
    const int*   s = (const int*)d_in[0];
    const int*   o = (const int*)d_in[1];
    const float* x = (const float*)d_in[2];
    float* out = (float*)d_out;

    const int n  = in_sizes[0];
    const int n4 = n >> 2;

    disc_loss_fused<<<RBLOCKS, RTHREADS>>>(s, o, x, n4, 1.0f / (float)n, out);
}